// round 6
// baseline (speedup 1.0000x reference)
#include <cuda_runtime.h>
#include <cuda_bf16.h>
#include <cstdint>

// TSM: x (B=4, T=16, H=64, W=64, C=256) fp32
// out[..., 0:64)    = x[t+1, ..., 0:64)   (0 at t=T-1)
// out[..., 64:128)  = x[t-1, ..., 64:128) (0 at t=0)
// out[..., 128:256) = x[t, ..., 128:256)
//
// R6: persistent grid (148 SMs x 8 CTAs) + grid-stride loop over the
// R5 warp-uniform tiles. Removes wave transitions / CTA launch churn;
// memory access pattern is byte-identical to R5:
//   tile = 1024 f4 = 16 pixels, aligned in a (b,t) slab (slab = 256 tiles).
//   Warp-tile (w,u) = pixels {2w,2w+1} x 16-f4 channel group u.
//   g0: dt=+1 (zero at t=15), g1: dt=-1 (zero at t=0), g2,g3: identity.

static constexpr int BTSTRIDE = 1 << 18;      // float4 per (b,t) slab
static constexpr int NTILES = 16384;          // total 1024-f4 tiles
static constexpr int TPB = 256;
static constexpr int GRID = 148 * 8;          // persistent: full residency

__global__ __launch_bounds__(TPB) void tsm_kernel(const float4* __restrict__ in,
                                                  float4* __restrict__ out)
{
    const int tid = threadIdx.x;
    const int w   = tid >> 5;
    const int l   = tid & 31;
    const int off = ((w << 1) + (l >> 4)) * 64 + (l & 15);

    for (int bid = blockIdx.x; bid < NTILES; bid += GRID) {
        const long long i0 = (long long)bid * 1024 + off;
        const int t = (bid >> 8) & 15;          // 256 tiles per slab

        float4 v0 = make_float4(0.f, 0.f, 0.f, 0.f);
        float4 v1 = make_float4(0.f, 0.f, 0.f, 0.f);

        if (t < 15) v0 = __ldcs(&in[i0 + BTSTRIDE]);
        if (t > 0)  v1 = __ldcs(&in[i0 + 16 - BTSTRIDE]);
        float4 v2 = __ldcs(&in[i0 + 32]);
        float4 v3 = __ldcs(&in[i0 + 48]);

        __stcs(&out[i0],      v0);
        __stcs(&out[i0 + 16], v1);
        __stcs(&out[i0 + 32], v2);
        __stcs(&out[i0 + 48], v3);
    }
}

extern "C" void kernel_launch(void* const* d_in, const int* in_sizes, int n_in,
                              void* d_out, int out_size)
{
    const float4* in = (const float4*)d_in[0];
    float4* out = (float4*)d_out;

    tsm_kernel<<<GRID, TPB>>>(in, out);
}

// round 7
// speedup vs baseline: 1.1226x; 1.1226x over previous
#include <cuda_runtime.h>
#include <cuda_bf16.h>
#include <cstdint>

// TSM: x (B=4, T=16, H=64, W=64, C=256) fp32
// out[..., 0:64)    = x[t+1, ..., 0:64)   (0 at t=T-1)
// out[..., 64:128)  = x[t-1, ..., 64:128) (0 at t=0)
// out[..., 128:256) = x[t, ..., 128:256)
//
// R7: revert to R3 structure (best: 73.54us kernel) — exact-fit grid,
// block-strided unroll x8, streaming stores — plus ld.global.cs.L2::256B
// prefetch hint on loads (256B L2 sector pairing for better DRAM row/burst
// efficiency on the three sequential read streams).
//
// float4 units: c4 = i & 63; t = (i >> 18) & 15; slab stride = 1<<18 float4.
// dt = +1 (c4<16), -1 (c4<32), 0 otherwise. Invalid src -> 0.

static constexpr int BTSTRIDE = 1 << 18;      // float4 per (b,t) slab
static constexpr long long N4 = 16777216LL;   // total float4
static constexpr int UNROLL = 8;
static constexpr int TPB = 256;
static constexpr int F4_PER_BLOCK = TPB * UNROLL; // 2048

__device__ __forceinline__ float4 ldg_cs_l2_256(const float4* p)
{
    float4 v;
    asm volatile("ld.global.cs.L2::256B.v4.f32 {%0,%1,%2,%3}, [%4];"
                 : "=f"(v.x), "=f"(v.y), "=f"(v.z), "=f"(v.w)
                 : "l"(p));
    return v;
}

__global__ __launch_bounds__(TPB) void tsm_kernel(const float4* __restrict__ in,
                                                  float4* __restrict__ out)
{
    long long blockBase = (long long)(blockIdx.x) * F4_PER_BLOCK;
    int tid = threadIdx.x;

    float4 v[UNROLL];

    #pragma unroll
    for (int u = 0; u < UNROLL; ++u) {
        long long i = blockBase + u * TPB + tid;
        int c4 = (int)(i & 63);
        int t  = (int)((i >> 18) & 15);

        int dt = (c4 < 16) ? 1 : ((c4 < 32) ? -1 : 0);
        int ts = t + dt;
        bool valid = (unsigned)ts < 16u;

        v[u] = make_float4(0.f, 0.f, 0.f, 0.f);
        if (valid) {
            v[u] = ldg_cs_l2_256(&in[i + (long long)dt * BTSTRIDE]);
        }
    }

    #pragma unroll
    for (int u = 0; u < UNROLL; ++u) {
        long long i = blockBase + u * TPB + tid;
        __stcs(&out[i], v[u]);
    }
}

extern "C" void kernel_launch(void* const* d_in, const int* in_sizes, int n_in,
                              void* d_out, int out_size)
{
    const float4* in = (const float4*)d_in[0];
    float4* out = (float4*)d_out;

    int blocks = (int)(N4 / F4_PER_BLOCK); // 8192
    tsm_kernel<<<blocks, TPB>>>(in, out);
}

// round 8
// speedup vs baseline: 1.1266x; 1.0036x over previous
#include <cuda_runtime.h>
#include <cuda_bf16.h>
#include <cstdint>

// TSM: x (B=4, T=16, H=64, W=64, C=256) fp32
// out[..., 0:64)    = x[t+1, ..., 0:64)   (0 at t=T-1)
// out[..., 64:128)  = x[t-1, ..., 64:128) (0 at t=0)
// out[..., 128:256) = x[t, ..., 128:256)
//
// FINAL (R3 config — best measured: 73.54us kernel / 80.35us bench).
// Evidence from R1-R7: six structurally distinct variants all plateau at
// 6.33-6.44 TB/s == the B300 LTS chip-throughput cap (~6300 B/cyc,
// path-independent). This kernel is memory-ceiling-bound; SM-side pipes
// are <9% utilized. Traffic is minimal: each byte touched once, boundary
// reads skipped, streaming (.cs) hints avoid L2 thrash on the 512MiB stream.
//
// float4 units: c4 = i & 63; t = (i >> 18) & 15; slab stride = 1<<18 float4.
// dt = +1 (c4<16), -1 (c4<32), 0 otherwise. Invalid src -> 0.
// Block-strided unroll x8: every LDG.128/STG.128 is perfectly coalesced
// (consecutive lanes -> consecutive float4), 8 independent loads in flight
// per thread before the store batch.

static constexpr int BTSTRIDE = 1 << 18;      // float4 per (b,t) slab
static constexpr long long N4 = 16777216LL;   // total float4
static constexpr int UNROLL = 8;
static constexpr int TPB = 256;
static constexpr int F4_PER_BLOCK = TPB * UNROLL; // 2048

__global__ __launch_bounds__(TPB) void tsm_kernel(const float4* __restrict__ in,
                                                  float4* __restrict__ out)
{
    long long blockBase = (long long)(blockIdx.x) * F4_PER_BLOCK;
    int tid = threadIdx.x;

    float4 v[UNROLL];

    #pragma unroll
    for (int u = 0; u < UNROLL; ++u) {
        long long i = blockBase + u * TPB + tid;
        int c4 = (int)(i & 63);
        int t  = (int)((i >> 18) & 15);

        int dt = (c4 < 16) ? 1 : ((c4 < 32) ? -1 : 0);
        int ts = t + dt;
        bool valid = (unsigned)ts < 16u;

        v[u] = make_float4(0.f, 0.f, 0.f, 0.f);
        if (valid) {
            v[u] = __ldcs(&in[i + (long long)dt * BTSTRIDE]);
        }
    }

    #pragma unroll
    for (int u = 0; u < UNROLL; ++u) {
        long long i = blockBase + u * TPB + tid;
        __stcs(&out[i], v[u]);
    }
}

extern "C" void kernel_launch(void* const* d_in, const int* in_sizes, int n_in,
                              void* d_out, int out_size)
{
    const float4* in = (const float4*)d_in[0];
    float4* out = (float4*)d_out;

    int blocks = (int)(N4 / F4_PER_BLOCK); // 8192
    tsm_kernel<<<blocks, TPB>>>(in, out);
}